// round 3
// baseline (speedup 1.0000x reference)
#include <cuda_runtime.h>

#define BN 8
#define HH 512
#define WW 512
#define HWSZ (HH*WW)        // 262144 = 2^18
#define NPIX (BN*HWSZ)      // 2097152
#define THREADS 256

// Scratch (device globals -- no allocation allowed)
__device__ int    g_par[2*NPIX];     // [0..NPIX) bg parents, [NPIX..2NPIX) fg parents
__device__ int    g_cnt[2*NPIX];     // component areas indexed by root
__device__ int    g_maxarea[2*BN];   // per-image max area: [0..BN)=bg, [BN..2BN)=fg
__device__ double g_S[6];            // S_fg[0..2], S_bg[0..2]
__device__ int    g_N[2];            // N_fg, N_bg

// ---------------- union-find (min-root, path-halving, race-safe) ----------------
// Invariant: P[x] <= x always and writes only decrease values -> no cycles, terminates.
__device__ __forceinline__ int uf_find(int* P, int x) {
    while (true) {
        int p = P[x];
        if (p == x) return x;
        int gp = P[p];
        if (gp == p) return p;
        atomicCAS(&P[x], p, gp);   // path halving; only succeeds if unchanged
        x = gp;
    }
}

__device__ __forceinline__ void uf_union(int* P, int a, int b) {
    int ra = uf_find(P, a);
    int rb = uf_find(P, b);
    while (ra != rb) {
        int hi = ra > rb ? ra : rb;
        int lo = (ra ^ rb) ^ hi;
        int old = atomicCAS(&P[hi], hi, lo);
        if (old == hi) return;
        ra = uf_find(P, old);
        rb = uf_find(P, lo);
    }
}

// ---------------- kernels ----------------

__global__ void k_init() {
    int t = blockIdx.x * blockDim.x + threadIdx.x;
    if (t < NPIX) {
        g_par[t]        = t;
        g_par[NPIX + t] = t;
        g_cnt[t]        = 0;
        g_cnt[NPIX + t] = 0;
    }
    if (t < 2*BN) g_maxarea[t] = 0;
    if (t < 6)    g_S[t] = 0.0;
    if (t < 2)    g_N[t] = 0;
}

__global__ void k_merge(const float* __restrict__ cam) {
    int t = blockIdx.x * blockDim.x + threadIdx.x;
    if (t >= NPIX) return;
    float c = cam[t];
    if (c < 0.2f) return;                  // fg mask implies bg mask (0.6 > 0.2)
    int p = t & (HWSZ - 1);
    bool hasL = (p & (WW - 1)) != 0;
    bool hasU = p >= WW;
    float cl = hasL ? cam[t - 1]  : -1.0f;
    float cu = hasU ? cam[t - WW] : -1.0f;
    if (cl >= 0.2f) uf_union(g_par, t, t - 1);
    if (cu >= 0.2f) uf_union(g_par, t, t - WW);
    if (c > 0.6f) {
        if (cl > 0.6f) uf_union(g_par + NPIX, t, t - 1);
        if (cu > 0.6f) uf_union(g_par + NPIX, t, t - WW);
    }
}

__global__ void k_count(const float* __restrict__ cam) {
    int t = blockIdx.x * blockDim.x + threadIdx.x;
    bool inb = t < NPIX;
    float c = inb ? cam[t] : -1.0f;
    int lane = threadIdx.x & 31;

    // bg: warp-aggregated atomics (giant-component hotspot mitigation)
    bool pred = inb && (c >= 0.2f);
    unsigned grp = __ballot_sync(0xffffffffu, pred);
    if (pred) {
        int r = uf_find(g_par, t);
        g_par[t] = r;                                   // full compression for k_ce
        unsigned m = __match_any_sync(grp, r);
        if (lane == __ffs(m) - 1) atomicAdd(&g_cnt[r], __popc(m));
    }
    // fg
    bool predf = inb && (c > 0.6f);
    unsigned grpf = __ballot_sync(0xffffffffu, predf);
    if (predf) {
        int r = uf_find(g_par + NPIX, t);
        g_par[NPIX + t] = r;
        unsigned m = __match_any_sync(grpf, r);
        if (lane == __ffs(m) - 1) atomicAdd(&g_cnt[NPIX + r], __popc(m));
    }
}

__global__ void k_maxarea() {
    int t = blockIdx.x * blockDim.x + threadIdx.x;
    int m0 = (t < NPIX) ? g_cnt[t] : 0;
    int m1 = (t < NPIX) ? g_cnt[NPIX + t] : 0;
    #pragma unroll
    for (int o = 16; o; o >>= 1) {
        m0 = max(m0, __shfl_down_sync(0xffffffffu, m0, o));
        m1 = max(m1, __shfl_down_sync(0xffffffffu, m1, o));
    }
    __shared__ int s0[8], s1[8];
    int w = threadIdx.x >> 5, lane = threadIdx.x & 31;
    if (lane == 0) { s0[w] = m0; s1[w] = m1; }
    __syncthreads();
    if (threadIdx.x == 0) {
        #pragma unroll
        for (int i = 1; i < 8; i++) { m0 = max(m0, s0[i]); m1 = max(m1, s1[i]); }
        int b = t >> 18;   // HWSZ = 2^18, block fully inside one image
        if (m0) atomicMax(&g_maxarea[b], m0);
        if (m1) atomicMax(&g_maxarea[BN + b], m1);
    }
}

__global__ void k_ce(const float* __restrict__ preds, const float* __restrict__ cam) {
    int t = blockIdx.x * blockDim.x + threadIdx.x;
    int b = t >> 18;
    int p = t & (HWSZ - 1);
    float c = cam[t];

    bool keep_bg = false, keep_fg = false;
    if (c >= 0.2f) {
        int r = g_par[t];
        keep_bg = 2 * g_cnt[r] > g_maxarea[b];
        if (c > 0.6f) {
            int rf = g_par[NPIX + t];
            keep_fg = 2 * g_cnt[NPIX + rf] > g_maxarea[BN + b];
        }
    }
    bool vfg = keep_fg;      // fg target valid (class 1) where kept
    bool vbg = !keep_bg;     // bg target valid (class 0) where NOT kept

    float s[6];
    #pragma unroll
    for (int i = 0; i < 3; i++) {
        const float* base = preds + (size_t)((i * BN + b) * 2) * HWSZ + p;
        float x0 = __ldg(base);
        float x1 = __ldg(base + HWSZ);
        float d  = x0 - x1;
        float l  = __logf(1.0f + __expf(-fabsf(d)));   // shared tail of both softplus
        s[i]     = vfg ? (fmaxf(d,  0.0f) + l) : 0.0f; // softplus(x0-x1) = -logp1
        s[3 + i] = vbg ? (fmaxf(-d, 0.0f) + l) : 0.0f; // softplus(x1-x0) = -logp0
    }
    int nf = vfg ? 1 : 0, nb = vbg ? 1 : 0;

    #pragma unroll
    for (int o = 16; o; o >>= 1) {
        #pragma unroll
        for (int k = 0; k < 6; k++) s[k] += __shfl_down_sync(0xffffffffu, s[k], o);
        nf += __shfl_down_sync(0xffffffffu, nf, o);
        nb += __shfl_down_sync(0xffffffffu, nb, o);
    }
    __shared__ float sh[8][6];
    __shared__ int   shn[8][2];
    int w = threadIdx.x >> 5, lane = threadIdx.x & 31;
    if (lane == 0) {
        #pragma unroll
        for (int k = 0; k < 6; k++) sh[w][k] = s[k];
        shn[w][0] = nf; shn[w][1] = nb;
    }
    __syncthreads();
    if (threadIdx.x == 0) {
        #pragma unroll
        for (int i = 1; i < 8; i++) {
            #pragma unroll
            for (int k = 0; k < 6; k++) s[k] += sh[i][k];
            nf += shn[i][0]; nb += shn[i][1];
        }
        #pragma unroll
        for (int k = 0; k < 6; k++) atomicAdd(&g_S[k], (double)s[k]);
        atomicAdd(&g_N[0], nf);
        atomicAdd(&g_N[1], nb);
    }
}

__global__ void k_final(float* out) {
    double nf = g_N[0] < 1 ? 1.0 : (double)g_N[0];
    double nb = g_N[1] < 1 ? 1.0 : (double)g_N[1];
    double loss = 0.0;
    #pragma unroll
    for (int i = 0; i < 3; i++) loss += g_S[i] / nf + g_S[3 + i] / nb;
    out[0] = (float)loss;
}

// ---------------- launch ----------------
extern "C" void kernel_launch(void* const* d_in, const int* in_sizes, int n_in,
                              void* d_out, int out_size) {
    const float* preds = (const float*)d_in[0];
    const float* cams  = (const float*)d_in[1];
    if (n_in >= 2 && in_sizes[0] == NPIX) {   // defensive: swapped metadata order
        preds = (const float*)d_in[1];
        cams  = (const float*)d_in[0];
    }
    int blocks = NPIX / THREADS;   // 8192
    k_init   <<<blocks, THREADS>>>();
    k_merge  <<<blocks, THREADS>>>(cams);
    k_count  <<<blocks, THREADS>>>(cams);
    k_maxarea<<<blocks, THREADS>>>();
    k_ce     <<<blocks, THREADS>>>(preds, cams);
    k_final  <<<1, 1>>>((float*)d_out);
}